// round 13
// baseline (speedup 1.0000x reference)
#include <cuda_runtime.h>
#include <cuda_bf16.h>
#include <cuda_fp16.h>
#include <math.h>
#include <cstdint>

#define BB 2
#define LL 2048
#define CC 1024
#define HH 16
#define DD 64
#define ML (BB*LL)

// ---------------- MMA / ldmatrix helpers ------------------------------------
__device__ __forceinline__ uint32_t smem_u32(const void* p) {
    uint32_t a;
    asm("{ .reg .u64 t; cvta.to.shared.u64 t, %1; cvt.u32.u64 %0, t; }" : "=r"(a) : "l"(p));
    return a;
}
__device__ __forceinline__ void ldsm4(uint32_t* r, uint32_t addr) {
    asm volatile("ldmatrix.sync.aligned.m8n8.x4.shared.b16 {%0,%1,%2,%3}, [%4];"
        : "=r"(r[0]), "=r"(r[1]), "=r"(r[2]), "=r"(r[3]) : "r"(addr));
}
__device__ __forceinline__ void ldsm4t(uint32_t* r, uint32_t addr) {
    asm volatile("ldmatrix.sync.aligned.m8n8.x4.trans.shared.b16 {%0,%1,%2,%3}, [%4];"
        : "=r"(r[0]), "=r"(r[1]), "=r"(r[2]), "=r"(r[3]) : "r"(addr));
}
__device__ __forceinline__ void mma_f16(float* c, const uint32_t* a, const uint32_t* b) {
    asm volatile("mma.sync.aligned.m16n8k16.row.col.f32.f16.f16.f32 "
        "{%0,%1,%2,%3}, {%4,%5,%6,%7}, {%8,%9}, {%0,%1,%2,%3};"
        : "+f"(c[0]), "+f"(c[1]), "+f"(c[2]), "+f"(c[3])
        : "r"(a[0]), "r"(a[1]), "r"(a[2]), "r"(a[3]), "r"(b[0]), "r"(b[1]));
}
__device__ __forceinline__ void cpasync16(uint32_t saddr, const void* g) {
    asm volatile("cp.async.cg.shared.global [%0], [%1], 16;" :: "r"(saddr), "l"(g));
}
#define CP_COMMIT() asm volatile("cp.async.commit_group;" ::: "memory")
#define CP_WAIT1()  asm volatile("cp.async.wait_group 1;" ::: "memory")
#define CP_WAIT0()  asm volatile("cp.async.wait_group 0;" ::: "memory")

// ---------------- scratch ----------------------------------------------------
__device__ __half g_qhh[BB*HH*LL*DD];     // fp16 Q heads
__device__ __half g_khh[BB*HH*LL*DD];
__device__ __half g_vhh[BB*HH*LL*DD];
__device__ float  g_bias[BB*LL];
__device__ float2 g_ropeTab[LL*32];
__device__ __half g_xhi[ML*CC], g_xlo[ML*CC];
__device__ __half g_w16[4*CC*CC];
__device__ __half g_ctxhi[ML*CC], g_ctxlo[ML*CC];

// ---------------- fused prep: split + weight cvt + mask bias + rope table ----
__global__ void prep_kernel(const float* __restrict__ q, const void* __restrict__ mp,
                            const float* __restrict__ w0, const float* __restrict__ w1,
                            const float* __restrict__ w2, const float* __restrict__ w3)
{
    const int bid = blockIdx.x;
    if (bid < 4096) {
        int i = (bid * 256 + threadIdx.x) * 4;
        float4 v = *(const float4*)(q + i);
        __half h0 = __float2half_rn(v.x), h1 = __float2half_rn(v.y);
        __half h2 = __float2half_rn(v.z), h3 = __float2half_rn(v.w);
        __half2 hp0; hp0.x = h0; hp0.y = h1;
        __half2 hp1; hp1.x = h2; hp1.y = h3;
        __half2 lp0; lp0.x = __float2half_rn(v.x - __half2float(h0));
        lp0.y = __float2half_rn(v.y - __half2float(h1));
        __half2 lp1; lp1.x = __float2half_rn(v.z - __half2float(h2));
        lp1.y = __float2half_rn(v.w - __half2float(h3));
        *(__half2*)(g_xhi + i)     = hp0;
        *(__half2*)(g_xhi + i + 2) = hp1;
        *(__half2*)(g_xlo + i)     = lp0;
        *(__half2*)(g_xlo + i + 2) = lp1;
    } else if (bid < 8192) {
        int t = bid - 4096;
        int ws = t >> 10;
        const float* in = (ws == 0) ? w0 : (ws == 1) ? w1 : (ws == 2) ? w2 : w3;
        __half* out = g_w16 + (size_t)ws * CC * CC;
        int i = ((t & 1023) * 256 + threadIdx.x) * 4;
        float4 v = *(const float4*)(in + i);
        *(__half2*)(out + i)     = __floats2half2_rn(v.x, v.y);
        *(__half2*)(out + i + 2) = __floats2half2_rn(v.z, v.w);
    } else if (bid < 8208) {
        __shared__ int s_i32, s_f32;
        if (threadIdx.x == 0) { s_i32 = 1; s_f32 = 1; }
        __syncthreads();
        const unsigned int* m = (const unsigned int*)mp;
        int i32 = 1, f32 = 1;
        for (int i = threadIdx.x; i < 1024; i += 256) {
            unsigned v = m[i];
            if (v > 1u) i32 = 0;
            if (v != 0u && v != 0x3F800000u) f32 = 0;
        }
        if (!i32) atomicAnd(&s_i32, 0);
        if (!f32) atomicAnd(&s_f32, 0);
        __syncthreads();
        int fmt = s_i32 ? 0 : (s_f32 ? 1 : 2);
        int i = (bid - 8192) * 256 + threadIdx.x;
        if (i < BB*LL) {
            bool on;
            if (fmt == 0)      on = ((const int*)mp)[i] != 0;
            else if (fmt == 1) on = ((const float*)mp)[i] != 0.0f;
            else               on = ((const unsigned char*)mp)[i] != 0;
            g_bias[i] = on ? 0.0f : -1e30f;
        }
    } else {
        int gid = (bid - 8208) * 256 + threadIdx.x;
        if (gid < LL*32) {
            int d = gid & 31, l = gid >> 5;
            double inv = exp(-10.819778284410283 * (double)(2 * d) / 64.0);  // ln(50000)
            double sn, cs;
            sincos((double)l * inv, &sn, &cs);
            g_ropeTab[gid] = make_float2((float)cs, (float)sn);
        }
    }
}

// ---------------- fp16 2-term HMMA NT GEMM ----------------------------------
#define TILE_B   10240
#define BUF_B    (3*TILE_B)
#define GM_SMEM  (2*BUF_B)     /* 61440 */

__global__ __launch_bounds__(256)
void gemm_mma_kernel(const __half* __restrict__ Ahi, const __half* __restrict__ Alo,
                     const __half* __restrict__ Wall,
                     const float* __restrict__ bias, float* __restrict__ oout, int is_oproj)
{
    extern __shared__ __align__(128) char smem[];
    const uint32_t sb = smem_u32(smem);
    const int tid  = threadIdx.x;
    const int warp = tid >> 5;
    const int lane = tid & 31;
    const int bm = blockIdx.y * 128;
    const int bn = blockIdx.x * 128;
    const int z  = blockIdx.z;

    const __half* Wp = Wall + (size_t)z * CC * CC;

#define LOAD_CHUNK(k0, bufbase)                                              \
    {                                                                        \
        _Pragma("unroll")                                                    \
        for (int j = 0; j < 6; j++) {                                        \
            const int tile = j >> 1;                                         \
            const int t = tid + (j & 1) * 256;                               \
            const int row = t >> 2, c16 = t & 3;                             \
            const __half* src = (tile == 0) ? Ahi : (tile == 1) ? Alo : Wp;  \
            const int baser = (tile < 2) ? bm : bn;                          \
            cpasync16((bufbase) + tile * TILE_B + row * 80 + c16 * 16,       \
                      src + (size_t)(baser + row) * CC + (k0) + c16 * 8);    \
        }                                                                    \
        CP_COMMIT();                                                         \
    }

    LOAD_CHUNK(0, sb)

    const int wm = (warp >> 2) * 64;
    const int wn = (warp & 3) * 32;
    uint32_t aoff[2][4][2];
#pragma unroll
    for (int dt = 0; dt < 2; dt++)
#pragma unroll
        for (int tm = 0; tm < 4; tm++)
#pragma unroll
            for (int ks = 0; ks < 2; ks++)
                aoff[dt][tm][ks] = sb + dt * TILE_B
                    + (wm + tm * 16 + (lane & 15)) * 80 + ks * 32 + (lane >> 4) * 16;
    uint32_t boff[4];
#pragma unroll
    for (int tn = 0; tn < 4; tn++)
        boff[tn] = sb + 2 * TILE_B
            + (wn + tn * 8 + (lane & 7)) * 80 + ((lane >> 3) & 3) * 16;

    float acc[4][4][4];
#pragma unroll
    for (int tm = 0; tm < 4; tm++)
#pragma unroll
        for (int tn = 0; tn < 4; tn++)
#pragma unroll
            for (int c = 0; c < 4; c++) acc[tm][tn][c] = 0.0f;

    int buf = 0;
    for (int ch = 0; ch < 32; ch++) {
        if (ch + 1 < 32) {
            LOAD_CHUNK((ch + 1) * 32, sb + (buf ^ 1) * BUF_B)
            CP_WAIT1();
        } else {
            CP_WAIT0();
        }
        __syncthreads();

        const uint32_t bo = buf * BUF_B;
        uint32_t bfrag[4][4];
#pragma unroll
        for (int tn = 0; tn < 4; tn++)
            ldsm4(bfrag[tn], boff[tn] + bo);
#pragma unroll
        for (int ks = 0; ks < 2; ks++) {
#pragma unroll
            for (int tm = 0; tm < 4; tm++) {
                uint32_t ah[4], al[4];
                ldsm4(ah, aoff[0][tm][ks] + bo);
                ldsm4(al, aoff[1][tm][ks] + bo);
#pragma unroll
                for (int tn = 0; tn < 4; tn++) {
                    mma_f16(acc[tm][tn], ah, &bfrag[tn][ks * 2]);
                    mma_f16(acc[tm][tn], al, &bfrag[tn][ks * 2]);
                }
            }
        }
        __syncthreads();
        buf ^= 1;
    }

    const int rbase = bm + wm + (lane >> 2);
    const int cbase = bn + wn + (lane & 3) * 2;
#pragma unroll
    for (int tm = 0; tm < 4; tm++) {
#pragma unroll
        for (int tn = 0; tn < 4; tn++) {
            int row0 = rbase + tm * 16;
            int col  = cbase + tn * 8;
            if (is_oproj) {
                float b0 = bias[col], b1 = bias[col + 1];
                *(float2*)&oout[(size_t)row0 * CC + col] =
                    make_float2(acc[tm][tn][0] + b0, acc[tm][tn][1] + b1);
                *(float2*)&oout[(size_t)(row0 + 8) * CC + col] =
                    make_float2(acc[tm][tn][2] + b0, acc[tm][tn][3] + b1);
            } else {
                __half* out = (z == 0) ? g_qhh : (z == 1) ? g_khh : g_vhh;
                const int h = col >> 6, d = col & 63;
                {
                    int b = row0 >> 11, l = row0 & (LL - 1);
                    *(__half2*)&out[(((size_t)b * HH + h) * LL + l) * DD + d] =
                        __floats2half2_rn(acc[tm][tn][0], acc[tm][tn][1]);
                }
                {
                    int r1 = row0 + 8;
                    int b = r1 >> 11, l = r1 & (LL - 1);
                    *(__half2*)&out[(((size_t)b * HH + h) * LL + l) * DD + d] =
                        __floats2half2_rn(acc[tm][tn][2], acc[tm][tn][3]);
                }
            }
        }
    }
}

// ---------------- RoPE apply: half2 vectorized, 0.125 folded into Q ----------
__global__ void rope_apply_kernel() {
    int gid = blockIdx.x * 256 + threadIdx.x;
    if (gid >= BB*HH*LL*16) return;
    int d2  = gid & 15;
    int row = gid >> 4;
    int l   = row & (LL - 1);
    int d0  = d2 * 2;
    float2 cs0 = g_ropeTab[l * 32 + d0];
    float2 cs1 = g_ropeTab[l * 32 + d0 + 1];
    __half* qp = g_qhh + (size_t)row * DD;
    __half* kp = g_khh + (size_t)row * DD;

    {
        float2 a = __half22float2(*(__half2*)(qp + d0));
        float2 b = __half22float2(*(__half2*)(qp + d0 + 32));
        *(__half2*)(qp + d0) = __floats2half2_rn(
            (a.x * cs0.x - b.x * cs0.y) * 0.125f,
            (a.y * cs1.x - b.y * cs1.y) * 0.125f);
        *(__half2*)(qp + d0 + 32) = __floats2half2_rn(
            (b.x * cs0.x + a.x * cs0.y) * 0.125f,
            (b.y * cs1.x + a.y * cs1.y) * 0.125f);
    }
    {
        float2 a = __half22float2(*(__half2*)(kp + d0));
        float2 b = __half22float2(*(__half2*)(kp + d0 + 32));
        *(__half2*)(kp + d0) = __floats2half2_rn(
            a.x * cs0.x - b.x * cs0.y,
            a.y * cs1.x - b.y * cs1.y);
        *(__half2*)(kp + d0 + 32) = __floats2half2_rn(
            b.x * cs0.x + a.x * cs0.y,
            b.y * cs1.x + a.y * cs1.y);
    }
}

// ---------------- Flash attention: fp16 HMMA + h2exp, 2 CTAs/SM --------------
#define FOFF_K  18432
#define FOFF_V  36864
#define FOFF_BI 55296
#define FL_SMEM 55808

__global__ __launch_bounds__(256, 2)
void flash_kernel()
{
    extern __shared__ __align__(128) char smx[];
    const uint32_t sb = smem_u32(smx);
    float* biasS = (float*)(smx + FOFF_BI);

    const int q0 = blockIdx.x * 128;
    const int bh = blockIdx.y;
    const int b  = bh >> 4;
    const int h  = bh & 15;
    const int tid  = threadIdx.x;
    const int warp = tid >> 5;
    const int lane = tid & 31;

    const __half* qb = g_qhh + (size_t)bh * LL * DD;
    const __half* kb = g_khh + (size_t)bh * LL * DD;
    const __half* vb = g_vhh + (size_t)bh * LL * DD;

    {
#pragma unroll
        for (int j = 0; j < 4; j++) {
            int t = tid + j * 256;
            int row = t >> 3, ch = t & 7;
            cpasync16(sb + row * 144 + ch * 16, qb + (size_t)(q0 + row) * DD + ch * 8);
        }
#pragma unroll
        for (int j = 0; j < 2; j++) {
            int t = tid + j * 256;
            int row = t >> 3, ch = t & 7;
            cpasync16(sb + FOFF_K + row * 144 + ch * 16, kb + (size_t)row * DD + ch * 8);
            cpasync16(sb + FOFF_V + row * 144 + ch * 16, vb + (size_t)row * DD + ch * 8);
        }
        if (tid < 64) biasS[tid] = g_bias[b * LL + tid];
        CP_COMMIT();
    }

    float O[8][4];
    float m0 = -1e30f, m1 = -1e30f, l0 = 0.0f, l1 = 0.0f;
#pragma unroll
    for (int nt = 0; nt < 8; nt++)
#pragma unroll
        for (int c = 0; c < 4; c++) O[nt][c] = 0.0f;

    uint32_t aQ[4][4];

    int buf = 0;
    for (int ch = 0; ch < 32; ch++) {
        if (ch + 1 < 32) {
            const int s1 = (ch + 1) * 64;
            const uint32_t ko = FOFF_K + (buf ^ 1) * 9216;
            const uint32_t vo = FOFF_V + (buf ^ 1) * 9216;
#pragma unroll
            for (int j = 0; j < 2; j++) {
                int t = tid + j * 256;
                int row = t >> 3, c16 = t & 7;
                cpasync16(sb + ko + row * 144 + c16 * 16, kb + (size_t)(s1 + row) * DD + c16 * 8);
                cpasync16(sb + vo + row * 144 + c16 * 16, vb + (size_t)(s1 + row) * DD + c16 * 8);
            }
            if (tid < 64) biasS[(buf ^ 1) * 64 + tid] = g_bias[b * LL + s1 + tid];
            CP_COMMIT();
            CP_WAIT1();
        } else {
            CP_WAIT0();
        }
        __syncthreads();

        if (ch == 0) {
#pragma unroll
            for (int kt = 0; kt < 4; kt++)
                ldsm4(aQ[kt], sb + (warp * 16 + (lane & 15)) * 144 + kt * 32 + (lane >> 4) * 16);
        }

        const uint32_t kOff = FOFF_K + buf * 9216;
        const uint32_t vOff = FOFF_V + buf * 9216;
        const float* bias_t = biasS + buf * 64;

        float S[8][4];
#pragma unroll
        for (int nt = 0; nt < 8; nt++)
#pragma unroll
            for (int c = 0; c < 4; c++) S[nt][c] = 0.0f;
#pragma unroll
        for (int ktp = 0; ktp < 2; ktp++) {
#pragma unroll
            for (int nt = 0; nt < 8; nt++) {
                uint32_t kB[4];
                ldsm4(kB, kOff + sb + (nt * 8 + (lane & 7)) * 144 + ktp * 64 + ((lane >> 3) & 3) * 16);
                mma_f16(S[nt], aQ[2 * ktp],     kB);
                mma_f16(S[nt], aQ[2 * ktp + 1], kB + 2);
            }
        }

        float rm0 = -1e30f, rm1 = -1e30f;
        float2 bv[8];
#pragma unroll
        for (int nt = 0; nt < 8; nt++) {
            bv[nt] = *(const float2*)&bias_t[nt * 8 + 2 * (lane & 3)];
            S[nt][0] += bv[nt].x;
            S[nt][1] += bv[nt].y;
            S[nt][2] += bv[nt].x;
            S[nt][3] += bv[nt].y;
            rm0 = fmaxf(rm0, fmaxf(S[nt][0], S[nt][1]));
            rm1 = fmaxf(rm1, fmaxf(S[nt][2], S[nt][3]));
        }
        rm0 = fmaxf(rm0, __shfl_xor_sync(0xffffffffu, rm0, 1));
        rm0 = fmaxf(rm0, __shfl_xor_sync(0xffffffffu, rm0, 2));
        rm1 = fmaxf(rm1, __shfl_xor_sync(0xffffffffu, rm1, 1));
        rm1 = fmaxf(rm1, __shfl_xor_sync(0xffffffffu, rm1, 2));
        float mn0 = fmaxf(m0, rm0), mn1 = fmaxf(m1, rm1);
        float sc0 = __expf(m0 - mn0), sc1 = __expf(m1 - mn1);
        m0 = mn0; m1 = mn1;

        uint32_t pe0[8], pe1[8];
        float rs0 = 0.0f, rs1 = 0.0f;
#pragma unroll
        for (int nt = 0; nt < 8; nt++) {
            __half2 e0 = h2exp(__floats2half2_rn(S[nt][0] - mn0, S[nt][1] - mn0));
            __half2 e1 = h2exp(__floats2half2_rn(S[nt][2] - mn1, S[nt][3] - mn1));
            pe0[nt] = *(uint32_t*)&e0;
            pe1[nt] = *(uint32_t*)&e1;
            float2 f0 = __half22float2(e0);
            float2 f1 = __half22float2(e1);
            rs0 += f0.x + f0.y;
            rs1 += f1.x + f1.y;
        }
        rs0 += __shfl_xor_sync(0xffffffffu, rs0, 1);
        rs0 += __shfl_xor_sync(0xffffffffu, rs0, 2);
        rs1 += __shfl_xor_sync(0xffffffffu, rs1, 1);
        rs1 += __shfl_xor_sync(0xffffffffu, rs1, 2);
        l0 = l0 * sc0 + rs0;
        l1 = l1 * sc1 + rs1;
#pragma unroll
        for (int nt = 0; nt < 8; nt++) {
            O[nt][0] *= sc0; O[nt][1] *= sc0;
            O[nt][2] *= sc1; O[nt][3] *= sc1;
        }

#pragma unroll
        for (int kt = 0; kt < 4; kt++) {
            uint32_t aP[4] = { pe0[2*kt], pe1[2*kt], pe0[2*kt+1], pe1[2*kt+1] };
#pragma unroll
            for (int np = 0; np < 4; np++) {
                uint32_t vB[4];
                ldsm4t(vB, vOff + sb + (kt * 16 + (lane & 15)) * 144 + np * 32 + (lane >> 4) * 16);
                mma_f16(O[np * 2],     aP, vB);
                mma_f16(O[np * 2 + 1], aP, vB + 2);
            }
        }
        __syncthreads();
        buf ^= 1;
    }

    // epilogue: normalize, write ctx as fp16 hi/lo
    const float il0 = 1.0f / l0, il1 = 1.0f / l1;
    const int row0 = q0 + warp * 16 + (lane >> 2);
    const size_t base0 = ((size_t)b * LL + row0) * CC + h * DD;
    const size_t base1 = base0 + (size_t)8 * CC;
#pragma unroll
    for (int nt = 0; nt < 8; nt++) {
        int col = nt * 8 + 2 * (lane & 3);
        {
            float o0 = O[nt][0] * il0, o1 = O[nt][1] * il0;
            __half h0 = __float2half_rn(o0), h1 = __float2half_rn(o1);
            __half2 hp; hp.x = h0; hp.y = h1;
            __half2 lp;
            lp.x = __float2half_rn(o0 - __half2float(h0));
            lp.y = __float2half_rn(o1 - __half2float(h1));
            *(__half2*)&g_ctxhi[base0 + col] = hp;
            *(__half2*)&g_ctxlo[base0 + col] = lp;
        }
        {
            float o0 = O[nt][2] * il1, o1 = O[nt][3] * il1;
            __half h0 = __float2half_rn(o0), h1 = __float2half_rn(o1);
            __half2 hp; hp.x = h0; hp.y = h1;
            __half2 lp;
            lp.x = __float2half_rn(o0 - __half2float(h0));
            lp.y = __float2half_rn(o1 - __half2float(h1));
            *(__half2*)&g_ctxhi[base1 + col] = hp;
            *(__half2*)&g_ctxlo[base1 + col] = lp;
        }
    }
}

// ---------------- launch -----------------------------------------------------
extern "C" void kernel_launch(void* const* d_in, const int* in_sizes, int n_in,
                              void* d_out, int out_size)
{
    const float* q  = (const float*)d_in[0];
    const void*  mk = d_in[1];
    const float* Wq = (const float*)d_in[2];
    const float* Wk = (const float*)d_in[3];
    const float* Wv = (const float*)d_in[4];
    const float* Wo = (const float*)d_in[5];
    const float* bo = (const float*)d_in[6];
    float* out = (float*)d_out;

    __half *xhi, *xlo, *w16, *chi, *clo;
    cudaGetSymbolAddress((void**)&xhi, g_xhi);
    cudaGetSymbolAddress((void**)&xlo, g_xlo);
    cudaGetSymbolAddress((void**)&w16, g_w16);
    cudaGetSymbolAddress((void**)&chi, g_ctxhi);
    cudaGetSymbolAddress((void**)&clo, g_ctxlo);

    cudaFuncSetAttribute(flash_kernel, cudaFuncAttributeMaxDynamicSharedMemorySize, FL_SMEM);
    cudaFuncSetAttribute(gemm_mma_kernel, cudaFuncAttributeMaxDynamicSharedMemorySize, GM_SMEM);

    prep_kernel<<<8464, 256>>>(q, mk, Wq, Wk, Wv, Wo);

    gemm_mma_kernel<<<dim3(CC/128, ML/128, 3), 256, GM_SMEM>>>(
        xhi, xlo, w16, nullptr, nullptr, 0);

    rope_apply_kernel<<<(BB*HH*LL*16 + 255) / 256, 256>>>();

    flash_kernel<<<dim3(LL/128, BB*HH), 256, FL_SMEM>>>();

    gemm_mma_kernel<<<dim3(CC/128, ML/128, 1), 256, GM_SMEM>>>(
        chi, clo, w16 + 3*(size_t)CC*CC, bo, out, 1);
}

// round 14
// speedup vs baseline: 1.5262x; 1.5262x over previous
#include <cuda_runtime.h>
#include <cuda_bf16.h>
#include <cuda_fp16.h>
#include <math.h>
#include <cstdint>

#define BB 2
#define LL 2048
#define CC 1024
#define HH 16
#define DD 64
#define ML (BB*LL)

// ---------------- MMA / ldmatrix helpers ------------------------------------
__device__ __forceinline__ uint32_t smem_u32(const void* p) {
    uint32_t a;
    asm("{ .reg .u64 t; cvta.to.shared.u64 t, %1; cvt.u32.u64 %0, t; }" : "=r"(a) : "l"(p));
    return a;
}
__device__ __forceinline__ void ldsm4(uint32_t* r, uint32_t addr) {
    asm volatile("ldmatrix.sync.aligned.m8n8.x4.shared.b16 {%0,%1,%2,%3}, [%4];"
        : "=r"(r[0]), "=r"(r[1]), "=r"(r[2]), "=r"(r[3]) : "r"(addr));
}
__device__ __forceinline__ void ldsm4t(uint32_t* r, uint32_t addr) {
    asm volatile("ldmatrix.sync.aligned.m8n8.x4.trans.shared.b16 {%0,%1,%2,%3}, [%4];"
        : "=r"(r[0]), "=r"(r[1]), "=r"(r[2]), "=r"(r[3]) : "r"(addr));
}
__device__ __forceinline__ void mma_f16(float* c, const uint32_t* a, const uint32_t* b) {
    asm volatile("mma.sync.aligned.m16n8k16.row.col.f32.f16.f16.f32 "
        "{%0,%1,%2,%3}, {%4,%5,%6,%7}, {%8,%9}, {%0,%1,%2,%3};"
        : "+f"(c[0]), "+f"(c[1]), "+f"(c[2]), "+f"(c[3])
        : "r"(a[0]), "r"(a[1]), "r"(a[2]), "r"(a[3]), "r"(b[0]), "r"(b[1]));
}
__device__ __forceinline__ void cpasync16(uint32_t saddr, const void* g) {
    asm volatile("cp.async.cg.shared.global [%0], [%1], 16;" :: "r"(saddr), "l"(g));
}
#define CP_COMMIT() asm volatile("cp.async.commit_group;" ::: "memory")
#define CP_WAIT1()  asm volatile("cp.async.wait_group 1;" ::: "memory")
#define CP_WAIT0()  asm volatile("cp.async.wait_group 0;" ::: "memory")

// ---------------- scratch ----------------------------------------------------
__device__ __half g_qhh[BB*HH*LL*DD];     // fp16 Q heads
__device__ __half g_khh[BB*HH*LL*DD];
__device__ __half g_vhh[BB*HH*LL*DD];
__device__ float  g_bias[BB*LL];
__device__ float2 g_ropeTab[LL*32];
__device__ __half g_xhi[ML*CC], g_xlo[ML*CC];
__device__ __half g_w16[4*CC*CC];
__device__ __half g_ctxhi[ML*CC], g_ctxlo[ML*CC];

// ---------------- fused prep: split + weight cvt + mask bias + rope table ----
__global__ void prep_kernel(const float* __restrict__ q, const void* __restrict__ mp,
                            const float* __restrict__ w0, const float* __restrict__ w1,
                            const float* __restrict__ w2, const float* __restrict__ w3)
{
    const int bid = blockIdx.x;
    if (bid < 4096) {
        int i = (bid * 256 + threadIdx.x) * 4;
        float4 v = *(const float4*)(q + i);
        __half h0 = __float2half_rn(v.x), h1 = __float2half_rn(v.y);
        __half h2 = __float2half_rn(v.z), h3 = __float2half_rn(v.w);
        __half2 hp0; hp0.x = h0; hp0.y = h1;
        __half2 hp1; hp1.x = h2; hp1.y = h3;
        __half2 lp0; lp0.x = __float2half_rn(v.x - __half2float(h0));
        lp0.y = __float2half_rn(v.y - __half2float(h1));
        __half2 lp1; lp1.x = __float2half_rn(v.z - __half2float(h2));
        lp1.y = __float2half_rn(v.w - __half2float(h3));
        *(__half2*)(g_xhi + i)     = hp0;
        *(__half2*)(g_xhi + i + 2) = hp1;
        *(__half2*)(g_xlo + i)     = lp0;
        *(__half2*)(g_xlo + i + 2) = lp1;
    } else if (bid < 8192) {
        int t = bid - 4096;
        int ws = t >> 10;
        const float* in = (ws == 0) ? w0 : (ws == 1) ? w1 : (ws == 2) ? w2 : w3;
        __half* out = g_w16 + (size_t)ws * CC * CC;
        int i = ((t & 1023) * 256 + threadIdx.x) * 4;
        float4 v = *(const float4*)(in + i);
        *(__half2*)(out + i)     = __floats2half2_rn(v.x, v.y);
        *(__half2*)(out + i + 2) = __floats2half2_rn(v.z, v.w);
    } else if (bid < 8208) {
        __shared__ int s_i32, s_f32;
        if (threadIdx.x == 0) { s_i32 = 1; s_f32 = 1; }
        __syncthreads();
        const unsigned int* m = (const unsigned int*)mp;
        int i32 = 1, f32 = 1;
        for (int i = threadIdx.x; i < 1024; i += 256) {
            unsigned v = m[i];
            if (v > 1u) i32 = 0;
            if (v != 0u && v != 0x3F800000u) f32 = 0;
        }
        if (!i32) atomicAnd(&s_i32, 0);
        if (!f32) atomicAnd(&s_f32, 0);
        __syncthreads();
        int fmt = s_i32 ? 0 : (s_f32 ? 1 : 2);
        int i = (bid - 8192) * 256 + threadIdx.x;
        if (i < BB*LL) {
            bool on;
            if (fmt == 0)      on = ((const int*)mp)[i] != 0;
            else if (fmt == 1) on = ((const float*)mp)[i] != 0.0f;
            else               on = ((const unsigned char*)mp)[i] != 0;
            g_bias[i] = on ? 0.0f : -1e30f;
        }
    } else {
        int gid = (bid - 8208) * 256 + threadIdx.x;
        if (gid < LL*32) {
            int d = gid & 31, l = gid >> 5;
            double inv = exp(-10.819778284410283 * (double)(2 * d) / 64.0);  // ln(50000)
            double sn, cs;
            sincos((double)l * inv, &sn, &cs);
            g_ropeTab[gid] = make_float2((float)cs, (float)sn);
        }
    }
}

// ---------------- fp16 2-term HMMA NT GEMM ----------------------------------
#define TILE_B   10240
#define BUF_B    (3*TILE_B)
#define GM_SMEM  (2*BUF_B)     /* 61440 */

__global__ __launch_bounds__(256)
void gemm_mma_kernel(const __half* __restrict__ Ahi, const __half* __restrict__ Alo,
                     const __half* __restrict__ Wall,
                     const float* __restrict__ bias, float* __restrict__ oout, int is_oproj)
{
    extern __shared__ __align__(128) char smem[];
    const uint32_t sb = smem_u32(smem);
    const int tid  = threadIdx.x;
    const int warp = tid >> 5;
    const int lane = tid & 31;
    const int bm = blockIdx.y * 128;
    const int bn = blockIdx.x * 128;
    const int z  = blockIdx.z;

    const __half* Wp = Wall + (size_t)z * CC * CC;

#define LOAD_CHUNK(k0, bufbase)                                              \
    {                                                                        \
        _Pragma("unroll")                                                    \
        for (int j = 0; j < 6; j++) {                                        \
            const int tile = j >> 1;                                         \
            const int t = tid + (j & 1) * 256;                               \
            const int row = t >> 2, c16 = t & 3;                             \
            const __half* src = (tile == 0) ? Ahi : (tile == 1) ? Alo : Wp;  \
            const int baser = (tile < 2) ? bm : bn;                          \
            cpasync16((bufbase) + tile * TILE_B + row * 80 + c16 * 16,       \
                      src + (size_t)(baser + row) * CC + (k0) + c16 * 8);    \
        }                                                                    \
        CP_COMMIT();                                                         \
    }

    LOAD_CHUNK(0, sb)

    const int wm = (warp >> 2) * 64;
    const int wn = (warp & 3) * 32;
    uint32_t aoff[2][4][2];
#pragma unroll
    for (int dt = 0; dt < 2; dt++)
#pragma unroll
        for (int tm = 0; tm < 4; tm++)
#pragma unroll
            for (int ks = 0; ks < 2; ks++)
                aoff[dt][tm][ks] = sb + dt * TILE_B
                    + (wm + tm * 16 + (lane & 15)) * 80 + ks * 32 + (lane >> 4) * 16;
    uint32_t boff[4];
#pragma unroll
    for (int tn = 0; tn < 4; tn++)
        boff[tn] = sb + 2 * TILE_B
            + (wn + tn * 8 + (lane & 7)) * 80 + ((lane >> 3) & 3) * 16;

    float acc[4][4][4];
#pragma unroll
    for (int tm = 0; tm < 4; tm++)
#pragma unroll
        for (int tn = 0; tn < 4; tn++)
#pragma unroll
            for (int c = 0; c < 4; c++) acc[tm][tn][c] = 0.0f;

    int buf = 0;
    for (int ch = 0; ch < 32; ch++) {
        if (ch + 1 < 32) {
            LOAD_CHUNK((ch + 1) * 32, sb + (buf ^ 1) * BUF_B)
            CP_WAIT1();
        } else {
            CP_WAIT0();
        }
        __syncthreads();

        const uint32_t bo = buf * BUF_B;
        uint32_t bfrag[4][4];
#pragma unroll
        for (int tn = 0; tn < 4; tn++)
            ldsm4(bfrag[tn], boff[tn] + bo);
#pragma unroll
        for (int ks = 0; ks < 2; ks++) {
#pragma unroll
            for (int tm = 0; tm < 4; tm++) {
                uint32_t ah[4], al[4];
                ldsm4(ah, aoff[0][tm][ks] + bo);
                ldsm4(al, aoff[1][tm][ks] + bo);
#pragma unroll
                for (int tn = 0; tn < 4; tn++) {
                    mma_f16(acc[tm][tn], ah, &bfrag[tn][ks * 2]);
                    mma_f16(acc[tm][tn], al, &bfrag[tn][ks * 2]);
                }
            }
        }
        __syncthreads();
        buf ^= 1;
    }

    const int rbase = bm + wm + (lane >> 2);
    const int cbase = bn + wn + (lane & 3) * 2;
#pragma unroll
    for (int tm = 0; tm < 4; tm++) {
#pragma unroll
        for (int tn = 0; tn < 4; tn++) {
            int row0 = rbase + tm * 16;
            int col  = cbase + tn * 8;
            if (is_oproj) {
                float b0 = bias[col], b1 = bias[col + 1];
                *(float2*)&oout[(size_t)row0 * CC + col] =
                    make_float2(acc[tm][tn][0] + b0, acc[tm][tn][1] + b1);
                *(float2*)&oout[(size_t)(row0 + 8) * CC + col] =
                    make_float2(acc[tm][tn][2] + b0, acc[tm][tn][3] + b1);
            } else {
                __half* out = (z == 0) ? g_qhh : (z == 1) ? g_khh : g_vhh;
                const int h = col >> 6, d = col & 63;
                {
                    int b = row0 >> 11, l = row0 & (LL - 1);
                    *(__half2*)&out[(((size_t)b * HH + h) * LL + l) * DD + d] =
                        __floats2half2_rn(acc[tm][tn][0], acc[tm][tn][1]);
                }
                {
                    int r1 = row0 + 8;
                    int b = r1 >> 11, l = r1 & (LL - 1);
                    *(__half2*)&out[(((size_t)b * HH + h) * LL + l) * DD + d] =
                        __floats2half2_rn(acc[tm][tn][2], acc[tm][tn][3]);
                }
            }
        }
    }
}

// ---------------- RoPE apply: half2 vectorized, 0.125 folded into Q ----------
__global__ void rope_apply_kernel() {
    int gid = blockIdx.x * 256 + threadIdx.x;
    if (gid >= BB*HH*LL*16) return;
    int d2  = gid & 15;
    int row = gid >> 4;
    int l   = row & (LL - 1);
    int d0  = d2 * 2;
    float2 cs0 = g_ropeTab[l * 32 + d0];
    float2 cs1 = g_ropeTab[l * 32 + d0 + 1];
    __half* qp = g_qhh + (size_t)row * DD;
    __half* kp = g_khh + (size_t)row * DD;

    {
        float2 a = __half22float2(*(__half2*)(qp + d0));
        float2 b = __half22float2(*(__half2*)(qp + d0 + 32));
        *(__half2*)(qp + d0) = __floats2half2_rn(
            (a.x * cs0.x - b.x * cs0.y) * 0.125f,
            (a.y * cs1.x - b.y * cs1.y) * 0.125f);
        *(__half2*)(qp + d0 + 32) = __floats2half2_rn(
            (b.x * cs0.x + a.x * cs0.y) * 0.125f,
            (b.y * cs1.x + a.y * cs1.y) * 0.125f);
    }
    {
        float2 a = __half22float2(*(__half2*)(kp + d0));
        float2 b = __half22float2(*(__half2*)(kp + d0 + 32));
        *(__half2*)(kp + d0) = __floats2half2_rn(
            a.x * cs0.x - b.x * cs0.y,
            a.y * cs1.x - b.y * cs1.y);
        *(__half2*)(kp + d0 + 32) = __floats2half2_rn(
            b.x * cs0.x + a.x * cs0.y,
            b.y * cs1.x + a.y * cs1.y);
    }
}

// ---------------- Flash attention: fp16 HMMA + h2exp, 2 CTAs/SM (no spill) ---
#define FOFF_K  18432
#define FOFF_V  36864
#define FOFF_BI 55296
#define FL_SMEM 55808

__global__ __launch_bounds__(256, 2)
void flash_kernel()
{
    extern __shared__ __align__(128) char smx[];
    const uint32_t sb = smem_u32(smx);
    float* biasS = (float*)(smx + FOFF_BI);

    const int q0 = blockIdx.x * 128;
    const int bh = blockIdx.y;
    const int b  = bh >> 4;
    const int h  = bh & 15;
    const int tid  = threadIdx.x;
    const int warp = tid >> 5;
    const int lane = tid & 31;

    const __half* qb = g_qhh + (size_t)bh * LL * DD;
    const __half* kb = g_khh + (size_t)bh * LL * DD;
    const __half* vb = g_vhh + (size_t)bh * LL * DD;

    {
#pragma unroll
        for (int j = 0; j < 4; j++) {
            int t = tid + j * 256;
            int row = t >> 3, ch = t & 7;
            cpasync16(sb + row * 144 + ch * 16, qb + (size_t)(q0 + row) * DD + ch * 8);
        }
#pragma unroll
        for (int j = 0; j < 2; j++) {
            int t = tid + j * 256;
            int row = t >> 3, ch = t & 7;
            cpasync16(sb + FOFF_K + row * 144 + ch * 16, kb + (size_t)row * DD + ch * 8);
            cpasync16(sb + FOFF_V + row * 144 + ch * 16, vb + (size_t)row * DD + ch * 8);
        }
        if (tid < 64) biasS[tid] = g_bias[b * LL + tid];
        CP_COMMIT();
    }

    float O[8][4];
    float m0 = -1e30f, m1 = -1e30f, l0 = 0.0f, l1 = 0.0f;
#pragma unroll
    for (int nt = 0; nt < 8; nt++)
#pragma unroll
        for (int c = 0; c < 4; c++) O[nt][c] = 0.0f;

    // Q fragment addresses (Q smem tile is persistent; fragments reloaded
    // per chunk to keep register count under the 2-CTA cap)
    const uint32_t qfr_base = sb + (warp * 16 + (lane & 15)) * 144 + (lane >> 4) * 16;

    int buf = 0;
    for (int ch = 0; ch < 32; ch++) {
        if (ch + 1 < 32) {
            const int s1 = (ch + 1) * 64;
            const uint32_t ko = FOFF_K + (buf ^ 1) * 9216;
            const uint32_t vo = FOFF_V + (buf ^ 1) * 9216;
#pragma unroll
            for (int j = 0; j < 2; j++) {
                int t = tid + j * 256;
                int row = t >> 3, c16 = t & 7;
                cpasync16(sb + ko + row * 144 + c16 * 16, kb + (size_t)(s1 + row) * DD + c16 * 8);
                cpasync16(sb + vo + row * 144 + c16 * 16, vb + (size_t)(s1 + row) * DD + c16 * 8);
            }
            if (tid < 64) biasS[(buf ^ 1) * 64 + tid] = g_bias[b * LL + s1 + tid];
            CP_COMMIT();
            CP_WAIT1();
        } else {
            CP_WAIT0();
        }
        __syncthreads();

        const uint32_t kOff = FOFF_K + buf * 9216;
        const uint32_t vOff = FOFF_V + buf * 9216;
        const float* bias_t = biasS + buf * 64;

        // ---- S = Q K^T (Q fragments reloaded per chunk: frees 16 regs)
        float S[8][4];
#pragma unroll
        for (int nt = 0; nt < 8; nt++)
#pragma unroll
            for (int c = 0; c < 4; c++) S[nt][c] = 0.0f;
#pragma unroll
        for (int ktp = 0; ktp < 2; ktp++) {
            uint32_t aQ0[4], aQ1[4];
            ldsm4(aQ0, qfr_base + (2 * ktp) * 32);
            ldsm4(aQ1, qfr_base + (2 * ktp + 1) * 32);
#pragma unroll
            for (int nt = 0; nt < 8; nt++) {
                uint32_t kB[4];
                ldsm4(kB, kOff + sb + (nt * 8 + (lane & 7)) * 144 + ktp * 64 + ((lane >> 3) & 3) * 16);
                mma_f16(S[nt], aQ0, kB);
                mma_f16(S[nt], aQ1, kB + 2);
            }
        }

        float rm0 = -1e30f, rm1 = -1e30f;
#pragma unroll
        for (int nt = 0; nt < 8; nt++) {
            float2 bv = *(const float2*)&bias_t[nt * 8 + 2 * (lane & 3)];
            S[nt][0] += bv.x;
            S[nt][1] += bv.y;
            S[nt][2] += bv.x;
            S[nt][3] += bv.y;
            rm0 = fmaxf(rm0, fmaxf(S[nt][0], S[nt][1]));
            rm1 = fmaxf(rm1, fmaxf(S[nt][2], S[nt][3]));
        }
        rm0 = fmaxf(rm0, __shfl_xor_sync(0xffffffffu, rm0, 1));
        rm0 = fmaxf(rm0, __shfl_xor_sync(0xffffffffu, rm0, 2));
        rm1 = fmaxf(rm1, __shfl_xor_sync(0xffffffffu, rm1, 1));
        rm1 = fmaxf(rm1, __shfl_xor_sync(0xffffffffu, rm1, 2));
        float mn0 = fmaxf(m0, rm0), mn1 = fmaxf(m1, rm1);
        float sc0 = __expf(m0 - mn0), sc1 = __expf(m1 - mn1);
        m0 = mn0; m1 = mn1;

        // exp (results packed back into S's register storage as uint pairs)
        uint32_t pe0[8], pe1[8];
        float rs0 = 0.0f, rs1 = 0.0f;
#pragma unroll
        for (int nt = 0; nt < 8; nt++) {
            __half2 e0 = h2exp(__floats2half2_rn(S[nt][0] - mn0, S[nt][1] - mn0));
            __half2 e1 = h2exp(__floats2half2_rn(S[nt][2] - mn1, S[nt][3] - mn1));
            pe0[nt] = *(uint32_t*)&e0;
            pe1[nt] = *(uint32_t*)&e1;
            float2 f0 = __half22float2(e0);
            float2 f1 = __half22float2(e1);
            rs0 += f0.x + f0.y;
            rs1 += f1.x + f1.y;
        }
        rs0 += __shfl_xor_sync(0xffffffffu, rs0, 1);
        rs0 += __shfl_xor_sync(0xffffffffu, rs0, 2);
        rs1 += __shfl_xor_sync(0xffffffffu, rs1, 1);
        rs1 += __shfl_xor_sync(0xffffffffu, rs1, 2);
        l0 = l0 * sc0 + rs0;
        l1 = l1 * sc1 + rs1;
#pragma unroll
        for (int nt = 0; nt < 8; nt++) {
            O[nt][0] *= sc0; O[nt][1] *= sc0;
            O[nt][2] *= sc1; O[nt][3] *= sc1;
        }

#pragma unroll
        for (int kt = 0; kt < 4; kt++) {
            uint32_t aP[4] = { pe0[2*kt], pe1[2*kt], pe0[2*kt+1], pe1[2*kt+1] };
#pragma unroll
            for (int np = 0; np < 4; np++) {
                uint32_t vB[4];
                ldsm4t(vB, vOff + sb + (kt * 16 + (lane & 15)) * 144 + np * 32 + (lane >> 4) * 16);
                mma_f16(O[np * 2],     aP, vB);
                mma_f16(O[np * 2 + 1], aP, vB + 2);
            }
        }
        __syncthreads();
        buf ^= 1;
    }

    // epilogue: normalize, write ctx as fp16 hi/lo
    const float il0 = 1.0f / l0, il1 = 1.0f / l1;
    const int row0 = q0 + warp * 16 + (lane >> 2);
    const size_t base0 = ((size_t)b * LL + row0) * CC + h * DD;
    const size_t base1 = base0 + (size_t)8 * CC;
#pragma unroll
    for (int nt = 0; nt < 8; nt++) {
        int col = nt * 8 + 2 * (lane & 3);
        {
            float o0 = O[nt][0] * il0, o1 = O[nt][1] * il0;
            __half h0 = __float2half_rn(o0), h1 = __float2half_rn(o1);
            __half2 hp; hp.x = h0; hp.y = h1;
            __half2 lp;
            lp.x = __float2half_rn(o0 - __half2float(h0));
            lp.y = __float2half_rn(o1 - __half2float(h1));
            *(__half2*)&g_ctxhi[base0 + col] = hp;
            *(__half2*)&g_ctxlo[base0 + col] = lp;
        }
        {
            float o0 = O[nt][2] * il1, o1 = O[nt][3] * il1;
            __half h0 = __float2half_rn(o0), h1 = __float2half_rn(o1);
            __half2 hp; hp.x = h0; hp.y = h1;
            __half2 lp;
            lp.x = __float2half_rn(o0 - __half2float(h0));
            lp.y = __float2half_rn(o1 - __half2float(h1));
            *(__half2*)&g_ctxhi[base1 + col] = hp;
            *(__half2*)&g_ctxlo[base1 + col] = lp;
        }
    }
}

// ---------------- launch -----------------------------------------------------
extern "C" void kernel_launch(void* const* d_in, const int* in_sizes, int n_in,
                              void* d_out, int out_size)
{
    const float* q  = (const float*)d_in[0];
    const void*  mk = d_in[1];
    const float* Wq = (const float*)d_in[2];
    const float* Wk = (const float*)d_in[3];
    const float* Wv = (const float*)d_in[4];
    const float* Wo = (const float*)d_in[5];
    const float* bo = (const float*)d_in[6];
    float* out = (float*)d_out;

    __half *xhi, *xlo, *w16, *chi, *clo;
    cudaGetSymbolAddress((void**)&xhi, g_xhi);
    cudaGetSymbolAddress((void**)&xlo, g_xlo);
    cudaGetSymbolAddress((void**)&w16, g_w16);
    cudaGetSymbolAddress((void**)&chi, g_ctxhi);
    cudaGetSymbolAddress((void**)&clo, g_ctxlo);

    cudaFuncSetAttribute(flash_kernel, cudaFuncAttributeMaxDynamicSharedMemorySize, FL_SMEM);
    cudaFuncSetAttribute(gemm_mma_kernel, cudaFuncAttributeMaxDynamicSharedMemorySize, GM_SMEM);

    prep_kernel<<<8464, 256>>>(q, mk, Wq, Wk, Wv, Wo);

    gemm_mma_kernel<<<dim3(CC/128, ML/128, 3), 256, GM_SMEM>>>(
        xhi, xlo, w16, nullptr, nullptr, 0);

    rope_apply_kernel<<<(BB*HH*LL*16 + 255) / 256, 256>>>();

    flash_kernel<<<dim3(LL/128, BB*HH), 256, FL_SMEM>>>();

    gemm_mma_kernel<<<dim3(CC/128, ML/128, 1), 256, GM_SMEM>>>(
        chi, clo, w16 + 3*(size_t)CC*CC, bo, out, 1);
}

// round 15
// speedup vs baseline: 1.5349x; 1.0057x over previous
#include <cuda_runtime.h>
#include <cuda_bf16.h>
#include <cuda_fp16.h>
#include <math.h>
#include <cstdint>

#define BB 2
#define LL 2048
#define CC 1024
#define HH 16
#define DD 64
#define ML (BB*LL)

// ---------------- MMA / ldmatrix helpers ------------------------------------
__device__ __forceinline__ uint32_t smem_u32(const void* p) {
    uint32_t a;
    asm("{ .reg .u64 t; cvta.to.shared.u64 t, %1; cvt.u32.u64 %0, t; }" : "=r"(a) : "l"(p));
    return a;
}
__device__ __forceinline__ void ldsm4(uint32_t* r, uint32_t addr) {
    asm volatile("ldmatrix.sync.aligned.m8n8.x4.shared.b16 {%0,%1,%2,%3}, [%4];"
        : "=r"(r[0]), "=r"(r[1]), "=r"(r[2]), "=r"(r[3]) : "r"(addr));
}
__device__ __forceinline__ void ldsm4t(uint32_t* r, uint32_t addr) {
    asm volatile("ldmatrix.sync.aligned.m8n8.x4.trans.shared.b16 {%0,%1,%2,%3}, [%4];"
        : "=r"(r[0]), "=r"(r[1]), "=r"(r[2]), "=r"(r[3]) : "r"(addr));
}
__device__ __forceinline__ void mma_f16(float* c, const uint32_t* a, const uint32_t* b) {
    asm volatile("mma.sync.aligned.m16n8k16.row.col.f32.f16.f16.f32 "
        "{%0,%1,%2,%3}, {%4,%5,%6,%7}, {%8,%9}, {%0,%1,%2,%3};"
        : "+f"(c[0]), "+f"(c[1]), "+f"(c[2]), "+f"(c[3])
        : "r"(a[0]), "r"(a[1]), "r"(a[2]), "r"(a[3]), "r"(b[0]), "r"(b[1]));
}
__device__ __forceinline__ void cpasync16(uint32_t saddr, const void* g) {
    asm volatile("cp.async.cg.shared.global [%0], [%1], 16;" :: "r"(saddr), "l"(g));
}
#define CP_COMMIT() asm volatile("cp.async.commit_group;" ::: "memory")
#define CP_WAIT1()  asm volatile("cp.async.wait_group 1;" ::: "memory")
#define CP_WAIT0()  asm volatile("cp.async.wait_group 0;" ::: "memory")

// ---------------- scratch ----------------------------------------------------
__device__ __half g_qhh[BB*HH*LL*DD];     // fp16 Q heads
__device__ __half g_khh[BB*HH*LL*DD];
__device__ __half g_vhh[BB*HH*LL*DD];
__device__ float  g_bias[BB*LL];
__device__ float2 g_ropeTab[LL*32];
__device__ __half g_xhi[ML*CC], g_xlo[ML*CC];
__device__ __half g_w16[4*CC*CC];
__device__ __half g_ctxhi[ML*CC], g_ctxlo[ML*CC];

// ---------------- fused prep: split + weight cvt + mask bias + rope table ----
__global__ void prep_kernel(const float* __restrict__ q, const void* __restrict__ mp,
                            const float* __restrict__ w0, const float* __restrict__ w1,
                            const float* __restrict__ w2, const float* __restrict__ w3)
{
    const int bid = blockIdx.x;
    if (bid < 4096) {
        int i = (bid * 256 + threadIdx.x) * 4;
        float4 v = *(const float4*)(q + i);
        __half h0 = __float2half_rn(v.x), h1 = __float2half_rn(v.y);
        __half h2 = __float2half_rn(v.z), h3 = __float2half_rn(v.w);
        __half2 hp0; hp0.x = h0; hp0.y = h1;
        __half2 hp1; hp1.x = h2; hp1.y = h3;
        __half2 lp0; lp0.x = __float2half_rn(v.x - __half2float(h0));
        lp0.y = __float2half_rn(v.y - __half2float(h1));
        __half2 lp1; lp1.x = __float2half_rn(v.z - __half2float(h2));
        lp1.y = __float2half_rn(v.w - __half2float(h3));
        *(__half2*)(g_xhi + i)     = hp0;
        *(__half2*)(g_xhi + i + 2) = hp1;
        *(__half2*)(g_xlo + i)     = lp0;
        *(__half2*)(g_xlo + i + 2) = lp1;
    } else if (bid < 8192) {
        int t = bid - 4096;
        int ws = t >> 10;
        const float* in = (ws == 0) ? w0 : (ws == 1) ? w1 : (ws == 2) ? w2 : w3;
        __half* out = g_w16 + (size_t)ws * CC * CC;
        int i = ((t & 1023) * 256 + threadIdx.x) * 4;
        float4 v = *(const float4*)(in + i);
        *(__half2*)(out + i)     = __floats2half2_rn(v.x, v.y);
        *(__half2*)(out + i + 2) = __floats2half2_rn(v.z, v.w);
    } else if (bid < 8208) {
        __shared__ int s_i32, s_f32;
        if (threadIdx.x == 0) { s_i32 = 1; s_f32 = 1; }
        __syncthreads();
        const unsigned int* m = (const unsigned int*)mp;
        int i32 = 1, f32 = 1;
        for (int i = threadIdx.x; i < 1024; i += 256) {
            unsigned v = m[i];
            if (v > 1u) i32 = 0;
            if (v != 0u && v != 0x3F800000u) f32 = 0;
        }
        if (!i32) atomicAnd(&s_i32, 0);
        if (!f32) atomicAnd(&s_f32, 0);
        __syncthreads();
        int fmt = s_i32 ? 0 : (s_f32 ? 1 : 2);
        int i = (bid - 8192) * 256 + threadIdx.x;
        if (i < BB*LL) {
            bool on;
            if (fmt == 0)      on = ((const int*)mp)[i] != 0;
            else if (fmt == 1) on = ((const float*)mp)[i] != 0.0f;
            else               on = ((const unsigned char*)mp)[i] != 0;
            g_bias[i] = on ? 0.0f : -1e30f;
        }
    } else {
        int gid = (bid - 8208) * 256 + threadIdx.x;
        if (gid < LL*32) {
            int d = gid & 31, l = gid >> 5;
            double inv = exp(-10.819778284410283 * (double)(2 * d) / 64.0);  // ln(50000)
            double sn, cs;
            sincos((double)l * inv, &sn, &cs);
            g_ropeTab[gid] = make_float2((float)cs, (float)sn);
        }
    }
}

// ---------------- fp16 2-term HMMA NT GEMM ----------------------------------
#define TILE_B   10240
#define BUF_B    (3*TILE_B)
#define GM_SMEM  (2*BUF_B)     /* 61440 */

__global__ __launch_bounds__(256)
void gemm_mma_kernel(const __half* __restrict__ Ahi, const __half* __restrict__ Alo,
                     const __half* __restrict__ Wall,
                     const float* __restrict__ bias, float* __restrict__ oout, int is_oproj)
{
    extern __shared__ __align__(128) char smem[];
    const uint32_t sb = smem_u32(smem);
    const int tid  = threadIdx.x;
    const int warp = tid >> 5;
    const int lane = tid & 31;
    const int bm = blockIdx.y * 128;
    const int bn = blockIdx.x * 128;
    const int z  = blockIdx.z;

    const __half* Wp = Wall + (size_t)z * CC * CC;

#define LOAD_CHUNK(k0, bufbase)                                              \
    {                                                                        \
        _Pragma("unroll")                                                    \
        for (int j = 0; j < 6; j++) {                                        \
            const int tile = j >> 1;                                         \
            const int t = tid + (j & 1) * 256;                               \
            const int row = t >> 2, c16 = t & 3;                             \
            const __half* src = (tile == 0) ? Ahi : (tile == 1) ? Alo : Wp;  \
            const int baser = (tile < 2) ? bm : bn;                          \
            cpasync16((bufbase) + tile * TILE_B + row * 80 + c16 * 16,       \
                      src + (size_t)(baser + row) * CC + (k0) + c16 * 8);    \
        }                                                                    \
        CP_COMMIT();                                                         \
    }

    LOAD_CHUNK(0, sb)

    const int wm = (warp >> 2) * 64;
    const int wn = (warp & 3) * 32;
    uint32_t aoff[2][4][2];
#pragma unroll
    for (int dt = 0; dt < 2; dt++)
#pragma unroll
        for (int tm = 0; tm < 4; tm++)
#pragma unroll
            for (int ks = 0; ks < 2; ks++)
                aoff[dt][tm][ks] = sb + dt * TILE_B
                    + (wm + tm * 16 + (lane & 15)) * 80 + ks * 32 + (lane >> 4) * 16;
    uint32_t boff[4];
#pragma unroll
    for (int tn = 0; tn < 4; tn++)
        boff[tn] = sb + 2 * TILE_B
            + (wn + tn * 8 + (lane & 7)) * 80 + ((lane >> 3) & 3) * 16;

    float acc[4][4][4];
#pragma unroll
    for (int tm = 0; tm < 4; tm++)
#pragma unroll
        for (int tn = 0; tn < 4; tn++)
#pragma unroll
            for (int c = 0; c < 4; c++) acc[tm][tn][c] = 0.0f;

    int buf = 0;
    for (int ch = 0; ch < 32; ch++) {
        if (ch + 1 < 32) {
            LOAD_CHUNK((ch + 1) * 32, sb + (buf ^ 1) * BUF_B)
            CP_WAIT1();
        } else {
            CP_WAIT0();
        }
        __syncthreads();

        const uint32_t bo = buf * BUF_B;
        uint32_t bfrag[4][4];
#pragma unroll
        for (int tn = 0; tn < 4; tn++)
            ldsm4(bfrag[tn], boff[tn] + bo);
#pragma unroll
        for (int ks = 0; ks < 2; ks++) {
#pragma unroll
            for (int tm = 0; tm < 4; tm++) {
                uint32_t ah[4], al[4];
                ldsm4(ah, aoff[0][tm][ks] + bo);
                ldsm4(al, aoff[1][tm][ks] + bo);
#pragma unroll
                for (int tn = 0; tn < 4; tn++) {
                    mma_f16(acc[tm][tn], ah, &bfrag[tn][ks * 2]);
                    mma_f16(acc[tm][tn], al, &bfrag[tn][ks * 2]);
                }
            }
        }
        __syncthreads();
        buf ^= 1;
    }

    const int rbase = bm + wm + (lane >> 2);
    const int cbase = bn + wn + (lane & 3) * 2;
#pragma unroll
    for (int tm = 0; tm < 4; tm++) {
#pragma unroll
        for (int tn = 0; tn < 4; tn++) {
            int row0 = rbase + tm * 16;
            int col  = cbase + tn * 8;
            if (is_oproj) {
                float b0 = bias[col], b1 = bias[col + 1];
                *(float2*)&oout[(size_t)row0 * CC + col] =
                    make_float2(acc[tm][tn][0] + b0, acc[tm][tn][1] + b1);
                *(float2*)&oout[(size_t)(row0 + 8) * CC + col] =
                    make_float2(acc[tm][tn][2] + b0, acc[tm][tn][3] + b1);
            } else {
                __half* out = (z == 0) ? g_qhh : (z == 1) ? g_khh : g_vhh;
                const int h = col >> 6, d = col & 63;
                {
                    int b = row0 >> 11, l = row0 & (LL - 1);
                    *(__half2*)&out[(((size_t)b * HH + h) * LL + l) * DD + d] =
                        __floats2half2_rn(acc[tm][tn][0], acc[tm][tn][1]);
                }
                {
                    int r1 = row0 + 8;
                    int b = r1 >> 11, l = r1 & (LL - 1);
                    *(__half2*)&out[(((size_t)b * HH + h) * LL + l) * DD + d] =
                        __floats2half2_rn(acc[tm][tn][2], acc[tm][tn][3]);
                }
            }
        }
    }
}

// ---------------- RoPE apply: half2 vectorized, 0.125 folded into Q ----------
__global__ void rope_apply_kernel() {
    int gid = blockIdx.x * 256 + threadIdx.x;
    if (gid >= BB*HH*LL*16) return;
    int d2  = gid & 15;
    int row = gid >> 4;
    int l   = row & (LL - 1);
    int d0  = d2 * 2;
    float2 cs0 = g_ropeTab[l * 32 + d0];
    float2 cs1 = g_ropeTab[l * 32 + d0 + 1];
    __half* qp = g_qhh + (size_t)row * DD;
    __half* kp = g_khh + (size_t)row * DD;

    {
        float2 a = __half22float2(*(__half2*)(qp + d0));
        float2 b = __half22float2(*(__half2*)(qp + d0 + 32));
        *(__half2*)(qp + d0) = __floats2half2_rn(
            (a.x * cs0.x - b.x * cs0.y) * 0.125f,
            (a.y * cs1.x - b.y * cs1.y) * 0.125f);
        *(__half2*)(qp + d0 + 32) = __floats2half2_rn(
            (b.x * cs0.x + a.x * cs0.y) * 0.125f,
            (b.y * cs1.x + a.y * cs1.y) * 0.125f);
    }
    {
        float2 a = __half22float2(*(__half2*)(kp + d0));
        float2 b = __half22float2(*(__half2*)(kp + d0 + 32));
        *(__half2*)(kp + d0) = __floats2half2_rn(
            a.x * cs0.x - b.x * cs0.y,
            a.y * cs1.x - b.y * cs1.y);
        *(__half2*)(kp + d0 + 32) = __floats2half2_rn(
            b.x * cs0.x + a.x * cs0.y,
            b.y * cs1.x + a.y * cs1.y);
    }
}

// ---------------- Flash attention: fp16 HMMA, exp interleaved into PV --------
#define FOFF_K  18432
#define FOFF_V  36864
#define FOFF_BI 55296
#define FL_SMEM 55808

__global__ __launch_bounds__(256, 2)
void flash_kernel()
{
    extern __shared__ __align__(128) char smx[];
    const uint32_t sb = smem_u32(smx);
    float* biasS = (float*)(smx + FOFF_BI);

    const int q0 = blockIdx.x * 128;
    const int bh = blockIdx.y;
    const int b  = bh >> 4;
    const int h  = bh & 15;
    const int tid  = threadIdx.x;
    const int warp = tid >> 5;
    const int lane = tid & 31;

    const __half* qb = g_qhh + (size_t)bh * LL * DD;
    const __half* kb = g_khh + (size_t)bh * LL * DD;
    const __half* vb = g_vhh + (size_t)bh * LL * DD;

    {
#pragma unroll
        for (int j = 0; j < 4; j++) {
            int t = tid + j * 256;
            int row = t >> 3, ch = t & 7;
            cpasync16(sb + row * 144 + ch * 16, qb + (size_t)(q0 + row) * DD + ch * 8);
        }
#pragma unroll
        for (int j = 0; j < 2; j++) {
            int t = tid + j * 256;
            int row = t >> 3, ch = t & 7;
            cpasync16(sb + FOFF_K + row * 144 + ch * 16, kb + (size_t)row * DD + ch * 8);
            cpasync16(sb + FOFF_V + row * 144 + ch * 16, vb + (size_t)row * DD + ch * 8);
        }
        if (tid < 64) biasS[tid] = g_bias[b * LL + tid];
        CP_COMMIT();
    }

    float O[8][4];
    float m0 = -1e30f, m1 = -1e30f, l0 = 0.0f, l1 = 0.0f;
#pragma unroll
    for (int nt = 0; nt < 8; nt++)
#pragma unroll
        for (int c = 0; c < 4; c++) O[nt][c] = 0.0f;

    // Q smem tile persistent; fragments reloaded per chunk (register diet)
    const uint32_t qfr_base = sb + (warp * 16 + (lane & 15)) * 144 + (lane >> 4) * 16;

    int buf = 0;
    for (int ch = 0; ch < 32; ch++) {
        if (ch + 1 < 32) {
            const int s1 = (ch + 1) * 64;
            const uint32_t ko = FOFF_K + (buf ^ 1) * 9216;
            const uint32_t vo = FOFF_V + (buf ^ 1) * 9216;
#pragma unroll
            for (int j = 0; j < 2; j++) {
                int t = tid + j * 256;
                int row = t >> 3, c16 = t & 7;
                cpasync16(sb + ko + row * 144 + c16 * 16, kb + (size_t)(s1 + row) * DD + c16 * 8);
                cpasync16(sb + vo + row * 144 + c16 * 16, vb + (size_t)(s1 + row) * DD + c16 * 8);
            }
            if (tid < 64) biasS[(buf ^ 1) * 64 + tid] = g_bias[b * LL + s1 + tid];
            CP_COMMIT();
            CP_WAIT1();
        } else {
            CP_WAIT0();
        }
        __syncthreads();

        const uint32_t kOff = FOFF_K + buf * 9216;
        const uint32_t vOff = FOFF_V + buf * 9216;
        const float* bias_t = biasS + buf * 64;

        // ---- S = Q K^T
        float S[8][4];
#pragma unroll
        for (int nt = 0; nt < 8; nt++)
#pragma unroll
            for (int c = 0; c < 4; c++) S[nt][c] = 0.0f;
#pragma unroll
        for (int ktp = 0; ktp < 2; ktp++) {
            uint32_t aQ0[4], aQ1[4];
            ldsm4(aQ0, qfr_base + (2 * ktp) * 32);
            ldsm4(aQ1, qfr_base + (2 * ktp + 1) * 32);
#pragma unroll
            for (int nt = 0; nt < 8; nt++) {
                uint32_t kB[4];
                ldsm4(kB, kOff + sb + (nt * 8 + (lane & 7)) * 144 + ktp * 64 + ((lane >> 3) & 3) * 16);
                mma_f16(S[nt], aQ0, kB);
                mma_f16(S[nt], aQ1, kB + 2);
            }
        }

        // ---- bias + running max
        float rm0 = -1e30f, rm1 = -1e30f;
#pragma unroll
        for (int nt = 0; nt < 8; nt++) {
            float2 bv = *(const float2*)&bias_t[nt * 8 + 2 * (lane & 3)];
            S[nt][0] += bv.x;
            S[nt][1] += bv.y;
            S[nt][2] += bv.x;
            S[nt][3] += bv.y;
            rm0 = fmaxf(rm0, fmaxf(S[nt][0], S[nt][1]));
            rm1 = fmaxf(rm1, fmaxf(S[nt][2], S[nt][3]));
        }
        rm0 = fmaxf(rm0, __shfl_xor_sync(0xffffffffu, rm0, 1));
        rm0 = fmaxf(rm0, __shfl_xor_sync(0xffffffffu, rm0, 2));
        rm1 = fmaxf(rm1, __shfl_xor_sync(0xffffffffu, rm1, 1));
        rm1 = fmaxf(rm1, __shfl_xor_sync(0xffffffffu, rm1, 2));
        float mn0 = fmaxf(m0, rm0), mn1 = fmaxf(m1, rm1);
        float sc0 = __expf(m0 - mn0), sc1 = __expf(m1 - mn1);
        m0 = mn0; m1 = mn1;

        // rescale O before accumulating this chunk's PV
#pragma unroll
        for (int nt = 0; nt < 8; nt++) {
            O[nt][0] *= sc0; O[nt][1] *= sc0;
            O[nt][2] *= sc1; O[nt][3] *= sc1;
        }

        // ---- exp interleaved into PV (aP live range = 4 regs per kt group)
        float rs0 = 0.0f, rs1 = 0.0f;
#pragma unroll
        for (int kt = 0; kt < 4; kt++) {
            uint32_t aP[4];
            {
                const int nt = 2 * kt;
                __half2 e0 = h2exp(__floats2half2_rn(S[nt][0] - mn0, S[nt][1] - mn0));
                __half2 e1 = h2exp(__floats2half2_rn(S[nt][2] - mn1, S[nt][3] - mn1));
                aP[0] = *(uint32_t*)&e0;
                aP[1] = *(uint32_t*)&e1;
                float2 f0 = __half22float2(e0);
                float2 f1 = __half22float2(e1);
                rs0 += f0.x + f0.y;
                rs1 += f1.x + f1.y;
            }
            {
                const int nt = 2 * kt + 1;
                __half2 e0 = h2exp(__floats2half2_rn(S[nt][0] - mn0, S[nt][1] - mn0));
                __half2 e1 = h2exp(__floats2half2_rn(S[nt][2] - mn1, S[nt][3] - mn1));
                aP[2] = *(uint32_t*)&e0;
                aP[3] = *(uint32_t*)&e1;
                float2 f0 = __half22float2(e0);
                float2 f1 = __half22float2(e1);
                rs0 += f0.x + f0.y;
                rs1 += f1.x + f1.y;
            }
#pragma unroll
            for (int np = 0; np < 4; np++) {
                uint32_t vB[4];
                ldsm4t(vB, vOff + sb + (kt * 16 + (lane & 15)) * 144 + np * 32 + (lane >> 4) * 16);
                mma_f16(O[np * 2],     aP, vB);
                mma_f16(O[np * 2 + 1], aP, vB + 2);
            }
        }
        rs0 += __shfl_xor_sync(0xffffffffu, rs0, 1);
        rs0 += __shfl_xor_sync(0xffffffffu, rs0, 2);
        rs1 += __shfl_xor_sync(0xffffffffu, rs1, 1);
        rs1 += __shfl_xor_sync(0xffffffffu, rs1, 2);
        l0 = l0 * sc0 + rs0;
        l1 = l1 * sc1 + rs1;

        __syncthreads();
        buf ^= 1;
    }

    // epilogue: normalize, write ctx as fp16 hi/lo
    const float il0 = 1.0f / l0, il1 = 1.0f / l1;
    const int row0 = q0 + warp * 16 + (lane >> 2);
    const size_t base0 = ((size_t)b * LL + row0) * CC + h * DD;
    const size_t base1 = base0 + (size_t)8 * CC;
#pragma unroll
    for (int nt = 0; nt < 8; nt++) {
        int col = nt * 8 + 2 * (lane & 3);
        {
            float o0 = O[nt][0] * il0, o1 = O[nt][1] * il0;
            __half h0 = __float2half_rn(o0), h1 = __float2half_rn(o1);
            __half2 hp; hp.x = h0; hp.y = h1;
            __half2 lp;
            lp.x = __float2half_rn(o0 - __half2float(h0));
            lp.y = __float2half_rn(o1 - __half2float(h1));
            *(__half2*)&g_ctxhi[base0 + col] = hp;
            *(__half2*)&g_ctxlo[base0 + col] = lp;
        }
        {
            float o0 = O[nt][2] * il1, o1 = O[nt][3] * il1;
            __half h0 = __float2half_rn(o0), h1 = __float2half_rn(o1);
            __half2 hp; hp.x = h0; hp.y = h1;
            __half2 lp;
            lp.x = __float2half_rn(o0 - __half2float(h0));
            lp.y = __float2half_rn(o1 - __half2float(h1));
            *(__half2*)&g_ctxhi[base1 + col] = hp;
            *(__half2*)&g_ctxlo[base1 + col] = lp;
        }
    }
}

// ---------------- launch -----------------------------------------------------
extern "C" void kernel_launch(void* const* d_in, const int* in_sizes, int n_in,
                              void* d_out, int out_size)
{
    const float* q  = (const float*)d_in[0];
    const void*  mk = d_in[1];
    const float* Wq = (const float*)d_in[2];
    const float* Wk = (const float*)d_in[3];
    const float* Wv = (const float*)d_in[4];
    const float* Wo = (const float*)d_in[5];
    const float* bo = (const float*)d_in[6];
    float* out = (float*)d_out;

    __half *xhi, *xlo, *w16, *chi, *clo;
    cudaGetSymbolAddress((void**)&xhi, g_xhi);
    cudaGetSymbolAddress((void**)&xlo, g_xlo);
    cudaGetSymbolAddress((void**)&w16, g_w16);
    cudaGetSymbolAddress((void**)&chi, g_ctxhi);
    cudaGetSymbolAddress((void**)&clo, g_ctxlo);

    cudaFuncSetAttribute(flash_kernel, cudaFuncAttributeMaxDynamicSharedMemorySize, FL_SMEM);
    cudaFuncSetAttribute(gemm_mma_kernel, cudaFuncAttributeMaxDynamicSharedMemorySize, GM_SMEM);

    prep_kernel<<<8464, 256>>>(q, mk, Wq, Wk, Wv, Wo);

    gemm_mma_kernel<<<dim3(CC/128, ML/128, 3), 256, GM_SMEM>>>(
        xhi, xlo, w16, nullptr, nullptr, 0);

    rope_apply_kernel<<<(BB*HH*LL*16 + 255) / 256, 256>>>();

    flash_kernel<<<dim3(LL/128, BB*HH), 256, FL_SMEM>>>();

    gemm_mma_kernel<<<dim3(CC/128, ML/128, 1), 256, GM_SMEM>>>(
        chi, clo, w16 + 3*(size_t)CC*CC, bo, out, 1);
}

// round 17
// speedup vs baseline: 1.6237x; 1.0579x over previous
#include <cuda_runtime.h>
#include <cuda_bf16.h>
#include <cuda_fp16.h>
#include <math.h>
#include <cstdint>

#define BB 2
#define LL 2048
#define CC 1024
#define HH 16
#define DD 64
#define ML (BB*LL)

// ---------------- MMA / ldmatrix helpers ------------------------------------
__device__ __forceinline__ uint32_t smem_u32(const void* p) {
    uint32_t a;
    asm("{ .reg .u64 t; cvta.to.shared.u64 t, %1; cvt.u32.u64 %0, t; }" : "=r"(a) : "l"(p));
    return a;
}
__device__ __forceinline__ void ldsm4(uint32_t* r, uint32_t addr) {
    asm volatile("ldmatrix.sync.aligned.m8n8.x4.shared.b16 {%0,%1,%2,%3}, [%4];"
        : "=r"(r[0]), "=r"(r[1]), "=r"(r[2]), "=r"(r[3]) : "r"(addr));
}
__device__ __forceinline__ void ldsm4t(uint32_t* r, uint32_t addr) {
    asm volatile("ldmatrix.sync.aligned.m8n8.x4.trans.shared.b16 {%0,%1,%2,%3}, [%4];"
        : "=r"(r[0]), "=r"(r[1]), "=r"(r[2]), "=r"(r[3]) : "r"(addr));
}
__device__ __forceinline__ void mma_f16(float* c, const uint32_t* a, const uint32_t* b) {
    asm volatile("mma.sync.aligned.m16n8k16.row.col.f32.f16.f16.f32 "
        "{%0,%1,%2,%3}, {%4,%5,%6,%7}, {%8,%9}, {%0,%1,%2,%3};"
        : "+f"(c[0]), "+f"(c[1]), "+f"(c[2]), "+f"(c[3])
        : "r"(a[0]), "r"(a[1]), "r"(a[2]), "r"(a[3]), "r"(b[0]), "r"(b[1]));
}
__device__ __forceinline__ void cpasync16(uint32_t saddr, const void* g) {
    asm volatile("cp.async.cg.shared.global [%0], [%1], 16;" :: "r"(saddr), "l"(g));
}
#define CP_COMMIT() asm volatile("cp.async.commit_group;" ::: "memory")
#define CP_WAIT1()  asm volatile("cp.async.wait_group 1;" ::: "memory")
#define CP_WAIT0()  asm volatile("cp.async.wait_group 0;" ::: "memory")

// ---------------- scratch ----------------------------------------------------
__device__ __half g_qhh[BB*HH*LL*DD];     // fp16 Q heads
__device__ __half g_khh[BB*HH*LL*DD];
__device__ __half g_vhh[BB*HH*LL*DD];
__device__ float  g_bias[BB*LL];
__device__ float2 g_ropeTab[LL*32];
__device__ __half g_xhi[ML*CC], g_xlo[ML*CC];
__device__ __half g_w16[4*CC*CC];
__device__ __half g_ctxhi[ML*CC], g_ctxlo[ML*CC];

// ---------------- fused prep: split + weight cvt + mask bias + rope table ----
__global__ void prep_kernel(const float* __restrict__ q, const void* __restrict__ mp,
                            const float* __restrict__ w0, const float* __restrict__ w1,
                            const float* __restrict__ w2, const float* __restrict__ w3)
{
    const int bid = blockIdx.x;
    if (bid < 4096) {
        int i = (bid * 256 + threadIdx.x) * 4;
        float4 v = *(const float4*)(q + i);
        __half h0 = __float2half_rn(v.x), h1 = __float2half_rn(v.y);
        __half h2 = __float2half_rn(v.z), h3 = __float2half_rn(v.w);
        __half2 hp0; hp0.x = h0; hp0.y = h1;
        __half2 hp1; hp1.x = h2; hp1.y = h3;
        __half2 lp0; lp0.x = __float2half_rn(v.x - __half2float(h0));
        lp0.y = __float2half_rn(v.y - __half2float(h1));
        __half2 lp1; lp1.x = __float2half_rn(v.z - __half2float(h2));
        lp1.y = __float2half_rn(v.w - __half2float(h3));
        *(__half2*)(g_xhi + i)     = hp0;
        *(__half2*)(g_xhi + i + 2) = hp1;
        *(__half2*)(g_xlo + i)     = lp0;
        *(__half2*)(g_xlo + i + 2) = lp1;
    } else if (bid < 8192) {
        int t = bid - 4096;
        int ws = t >> 10;
        const float* in = (ws == 0) ? w0 : (ws == 1) ? w1 : (ws == 2) ? w2 : w3;
        __half* out = g_w16 + (size_t)ws * CC * CC;
        int i = ((t & 1023) * 256 + threadIdx.x) * 4;
        float4 v = *(const float4*)(in + i);
        *(__half2*)(out + i)     = __floats2half2_rn(v.x, v.y);
        *(__half2*)(out + i + 2) = __floats2half2_rn(v.z, v.w);
    } else if (bid < 8208) {
        __shared__ int s_i32, s_f32;
        if (threadIdx.x == 0) { s_i32 = 1; s_f32 = 1; }
        __syncthreads();
        const unsigned int* m = (const unsigned int*)mp;
        int i32 = 1, f32 = 1;
        for (int i = threadIdx.x; i < 1024; i += 256) {
            unsigned v = m[i];
            if (v > 1u) i32 = 0;
            if (v != 0u && v != 0x3F800000u) f32 = 0;
        }
        if (!i32) atomicAnd(&s_i32, 0);
        if (!f32) atomicAnd(&s_f32, 0);
        __syncthreads();
        int fmt = s_i32 ? 0 : (s_f32 ? 1 : 2);
        int i = (bid - 8192) * 256 + threadIdx.x;
        if (i < BB*LL) {
            bool on;
            if (fmt == 0)      on = ((const int*)mp)[i] != 0;
            else if (fmt == 1) on = ((const float*)mp)[i] != 0.0f;
            else               on = ((const unsigned char*)mp)[i] != 0;
            g_bias[i] = on ? 0.0f : -1e30f;
        }
    } else {
        int gid = (bid - 8208) * 256 + threadIdx.x;
        if (gid < LL*32) {
            int d = gid & 31, l = gid >> 5;
            double inv = exp(-10.819778284410283 * (double)(2 * d) / 64.0);  // ln(50000)
            double sn, cs;
            sincos((double)l * inv, &sn, &cs);
            g_ropeTab[gid] = make_float2((float)cs, (float)sn);
        }
    }
}

// ---------------- fp16 2-term HMMA NT GEMM ----------------------------------
#define TILE_B   10240
#define BUF_B    (3*TILE_B)
#define GM_SMEM  (2*BUF_B)     /* 61440 */

__global__ __launch_bounds__(256)
void gemm_mma_kernel(const __half* __restrict__ Ahi, const __half* __restrict__ Alo,
                     const __half* __restrict__ Wall,
                     const float* __restrict__ bias, float* __restrict__ oout, int is_oproj)
{
    extern __shared__ __align__(128) char smem[];
    const uint32_t sb = smem_u32(smem);
    const int tid  = threadIdx.x;
    const int warp = tid >> 5;
    const int lane = tid & 31;
    const int bm = blockIdx.y * 128;
    const int bn = blockIdx.x * 128;
    const int z  = blockIdx.z;

    const __half* Wp = Wall + (size_t)z * CC * CC;

#define LOAD_CHUNK(k0, bufbase)                                              \
    {                                                                        \
        _Pragma("unroll")                                                    \
        for (int j = 0; j < 6; j++) {                                        \
            const int tile = j >> 1;                                         \
            const int t = tid + (j & 1) * 256;                               \
            const int row = t >> 2, c16 = t & 3;                             \
            const __half* src = (tile == 0) ? Ahi : (tile == 1) ? Alo : Wp;  \
            const int baser = (tile < 2) ? bm : bn;                          \
            cpasync16((bufbase) + tile * TILE_B + row * 80 + c16 * 16,       \
                      src + (size_t)(baser + row) * CC + (k0) + c16 * 8);    \
        }                                                                    \
        CP_COMMIT();                                                         \
    }

    LOAD_CHUNK(0, sb)

    const int wm = (warp >> 2) * 64;
    const int wn = (warp & 3) * 32;
    uint32_t aoff[2][4][2];
#pragma unroll
    for (int dt = 0; dt < 2; dt++)
#pragma unroll
        for (int tm = 0; tm < 4; tm++)
#pragma unroll
            for (int ks = 0; ks < 2; ks++)
                aoff[dt][tm][ks] = sb + dt * TILE_B
                    + (wm + tm * 16 + (lane & 15)) * 80 + ks * 32 + (lane >> 4) * 16;
    uint32_t boff[4];
#pragma unroll
    for (int tn = 0; tn < 4; tn++)
        boff[tn] = sb + 2 * TILE_B
            + (wn + tn * 8 + (lane & 7)) * 80 + ((lane >> 3) & 3) * 16;

    float acc[4][4][4];
#pragma unroll
    for (int tm = 0; tm < 4; tm++)
#pragma unroll
        for (int tn = 0; tn < 4; tn++)
#pragma unroll
            for (int c = 0; c < 4; c++) acc[tm][tn][c] = 0.0f;

    int buf = 0;
    for (int ch = 0; ch < 32; ch++) {
        if (ch + 1 < 32) {
            LOAD_CHUNK((ch + 1) * 32, sb + (buf ^ 1) * BUF_B)
            CP_WAIT1();
        } else {
            CP_WAIT0();
        }
        __syncthreads();

        const uint32_t bo = buf * BUF_B;
        uint32_t bfrag[4][4];
#pragma unroll
        for (int tn = 0; tn < 4; tn++)
            ldsm4(bfrag[tn], boff[tn] + bo);
#pragma unroll
        for (int ks = 0; ks < 2; ks++) {
#pragma unroll
            for (int tm = 0; tm < 4; tm++) {
                uint32_t ah[4], al[4];
                ldsm4(ah, aoff[0][tm][ks] + bo);
                ldsm4(al, aoff[1][tm][ks] + bo);
#pragma unroll
                for (int tn = 0; tn < 4; tn++) {
                    mma_f16(acc[tm][tn], ah, &bfrag[tn][ks * 2]);
                    mma_f16(acc[tm][tn], al, &bfrag[tn][ks * 2]);
                }
            }
        }
        __syncthreads();
        buf ^= 1;
    }

    const int rbase = bm + wm + (lane >> 2);
    const int cbase = bn + wn + (lane & 3) * 2;
#pragma unroll
    for (int tm = 0; tm < 4; tm++) {
#pragma unroll
        for (int tn = 0; tn < 4; tn++) {
            int row0 = rbase + tm * 16;
            int col  = cbase + tn * 8;
            if (is_oproj) {
                float b0 = bias[col], b1 = bias[col + 1];
                *(float2*)&oout[(size_t)row0 * CC + col] =
                    make_float2(acc[tm][tn][0] + b0, acc[tm][tn][1] + b1);
                *(float2*)&oout[(size_t)(row0 + 8) * CC + col] =
                    make_float2(acc[tm][tn][2] + b0, acc[tm][tn][3] + b1);
            } else {
                __half* out = (z == 0) ? g_qhh : (z == 1) ? g_khh : g_vhh;
                const int h = col >> 6, d = col & 63;
                {
                    int b = row0 >> 11, l = row0 & (LL - 1);
                    *(__half2*)&out[(((size_t)b * HH + h) * LL + l) * DD + d] =
                        __floats2half2_rn(acc[tm][tn][0], acc[tm][tn][1]);
                }
                {
                    int r1 = row0 + 8;
                    int b = r1 >> 11, l = r1 & (LL - 1);
                    *(__half2*)&out[(((size_t)b * HH + h) * LL + l) * DD + d] =
                        __floats2half2_rn(acc[tm][tn][2], acc[tm][tn][3]);
                }
            }
        }
    }
}

// ---------------- RoPE apply: half2 vectorized, 0.125 folded into Q ----------
__global__ void rope_apply_kernel() {
    int gid = blockIdx.x * 256 + threadIdx.x;
    if (gid >= BB*HH*LL*16) return;
    int d2  = gid & 15;
    int row = gid >> 4;
    int l   = row & (LL - 1);
    int d0  = d2 * 2;
    float2 cs0 = g_ropeTab[l * 32 + d0];
    float2 cs1 = g_ropeTab[l * 32 + d0 + 1];
    __half* qp = g_qhh + (size_t)row * DD;
    __half* kp = g_khh + (size_t)row * DD;

    {
        float2 a = __half22float2(*(__half2*)(qp + d0));
        float2 b = __half22float2(*(__half2*)(qp + d0 + 32));
        *(__half2*)(qp + d0) = __floats2half2_rn(
            (a.x * cs0.x - b.x * cs0.y) * 0.125f,
            (a.y * cs1.x - b.y * cs1.y) * 0.125f);
        *(__half2*)(qp + d0 + 32) = __floats2half2_rn(
            (b.x * cs0.x + a.x * cs0.y) * 0.125f,
            (b.y * cs1.x + a.y * cs1.y) * 0.125f);
    }
    {
        float2 a = __half22float2(*(__half2*)(kp + d0));
        float2 b = __half22float2(*(__half2*)(kp + d0 + 32));
        *(__half2*)(kp + d0) = __floats2half2_rn(
            a.x * cs0.x - b.x * cs0.y,
            a.y * cs1.x - b.y * cs1.y);
        *(__half2*)(kp + d0 + 32) = __floats2half2_rn(
            b.x * cs0.x + a.x * cs0.y,
            b.y * cs1.x + a.y * cs1.y);
    }
}

// ---------------- Flash attention: 128-thr CTA, 64-row Q tile, 4 CTAs/SM -----
// smem: Q 64x144=9216 | K 2x9216 | V 2x9216 | bias 2x64xf32
#define FOFF_K  9216
#define FOFF_V  27648
#define FOFF_BI 46080
#define FL_SMEM 46592

__global__ __launch_bounds__(128, 4)
void flash_kernel()
{
    extern __shared__ __align__(128) char smx[];
    const uint32_t sb = smem_u32(smx);
    float* biasS = (float*)(smx + FOFF_BI);

    const int q0 = blockIdx.x * 64;
    const int bh = blockIdx.y;
    const int b  = bh >> 4;
    const int h  = bh & 15;
    const int tid  = threadIdx.x;
    const int warp = tid >> 5;
    const int lane = tid & 31;

    const __half* qb = g_qhh + (size_t)bh * LL * DD;
    const __half* kb = g_khh + (size_t)bh * LL * DD;
    const __half* vb = g_vhh + (size_t)bh * LL * DD;

    // stage Q (64 rows) + K/V tile 0
    {
#pragma unroll
        for (int j = 0; j < 4; j++) {
            int t = tid + j * 128;              // 512 tasks
            int row = t >> 3, ch = t & 7;
            cpasync16(sb + row * 144 + ch * 16, qb + (size_t)(q0 + row) * DD + ch * 8);
        }
#pragma unroll
        for (int j = 0; j < 4; j++) {
            int t = tid + j * 128;              // 512 tasks each
            int row = t >> 3, ch = t & 7;
            cpasync16(sb + FOFF_K + row * 144 + ch * 16, kb + (size_t)row * DD + ch * 8);
            cpasync16(sb + FOFF_V + row * 144 + ch * 16, vb + (size_t)row * DD + ch * 8);
        }
        if (tid < 64) biasS[tid] = g_bias[b * LL + tid];
        CP_COMMIT();
    }

    float O[8][4];
    float m0 = -1e30f, m1 = -1e30f, l0 = 0.0f, l1 = 0.0f;
#pragma unroll
    for (int nt = 0; nt < 8; nt++)
#pragma unroll
        for (int c = 0; c < 4; c++) O[nt][c] = 0.0f;

    // Q smem tile persistent; fragments reloaded per chunk (register diet)
    const uint32_t qfr_base = sb + (warp * 16 + (lane & 15)) * 144 + (lane >> 4) * 16;

    int buf = 0;
    for (int ch = 0; ch < 32; ch++) {
        if (ch + 1 < 32) {
            const int s1 = (ch + 1) * 64;
            const uint32_t ko = FOFF_K + (buf ^ 1) * 9216;
            const uint32_t vo = FOFF_V + (buf ^ 1) * 9216;
#pragma unroll
            for (int j = 0; j < 4; j++) {
                int t = tid + j * 128;
                int row = t >> 3, c16 = t & 7;
                cpasync16(sb + ko + row * 144 + c16 * 16, kb + (size_t)(s1 + row) * DD + c16 * 8);
                cpasync16(sb + vo + row * 144 + c16 * 16, vb + (size_t)(s1 + row) * DD + c16 * 8);
            }
            if (tid < 64) biasS[(buf ^ 1) * 64 + tid] = g_bias[b * LL + s1 + tid];
            CP_COMMIT();
            CP_WAIT1();
        } else {
            CP_WAIT0();
        }
        __syncthreads();

        const uint32_t kOff = FOFF_K + buf * 9216;
        const uint32_t vOff = FOFF_V + buf * 9216;
        const float* bias_t = biasS + buf * 64;

        // ---- S = Q K^T
        float S[8][4];
#pragma unroll
        for (int nt = 0; nt < 8; nt++)
#pragma unroll
            for (int c = 0; c < 4; c++) S[nt][c] = 0.0f;
#pragma unroll
        for (int ktp = 0; ktp < 2; ktp++) {
            uint32_t aQ0[4], aQ1[4];
            ldsm4(aQ0, qfr_base + (2 * ktp) * 32);
            ldsm4(aQ1, qfr_base + (2 * ktp + 1) * 32);
#pragma unroll
            for (int nt = 0; nt < 8; nt++) {
                uint32_t kB[4];
                ldsm4(kB, kOff + sb + (nt * 8 + (lane & 7)) * 144 + ktp * 64 + ((lane >> 3) & 3) * 16);
                mma_f16(S[nt], aQ0, kB);
                mma_f16(S[nt], aQ1, kB + 2);
            }
        }

        // ---- bias + running max
        float rm0 = -1e30f, rm1 = -1e30f;
#pragma unroll
        for (int nt = 0; nt < 8; nt++) {
            float2 bv = *(const float2*)&bias_t[nt * 8 + 2 * (lane & 3)];
            S[nt][0] += bv.x;
            S[nt][1] += bv.y;
            S[nt][2] += bv.x;
            S[nt][3] += bv.y;
            rm0 = fmaxf(rm0, fmaxf(S[nt][0], S[nt][1]));
            rm1 = fmaxf(rm1, fmaxf(S[nt][2], S[nt][3]));
        }
        rm0 = fmaxf(rm0, __shfl_xor_sync(0xffffffffu, rm0, 1));
        rm0 = fmaxf(rm0, __shfl_xor_sync(0xffffffffu, rm0, 2));
        rm1 = fmaxf(rm1, __shfl_xor_sync(0xffffffffu, rm1, 1));
        rm1 = fmaxf(rm1, __shfl_xor_sync(0xffffffffu, rm1, 2));
        float mn0 = fmaxf(m0, rm0), mn1 = fmaxf(m1, rm1);
        float sc0 = __expf(m0 - mn0), sc1 = __expf(m1 - mn1);
        m0 = mn0; m1 = mn1;

        // rescale O before accumulating this chunk's PV
#pragma unroll
        for (int nt = 0; nt < 8; nt++) {
            O[nt][0] *= sc0; O[nt][1] *= sc0;
            O[nt][2] *= sc1; O[nt][3] *= sc1;
        }

        // ---- exp interleaved into PV
        float rs0 = 0.0f, rs1 = 0.0f;
#pragma unroll
        for (int kt = 0; kt < 4; kt++) {
            uint32_t aP[4];
            {
                const int nt = 2 * kt;
                __half2 e0 = h2exp(__floats2half2_rn(S[nt][0] - mn0, S[nt][1] - mn0));
                __half2 e1 = h2exp(__floats2half2_rn(S[nt][2] - mn1, S[nt][3] - mn1));
                aP[0] = *(uint32_t*)&e0;
                aP[1] = *(uint32_t*)&e1;
                float2 f0 = __half22float2(e0);
                float2 f1 = __half22float2(e1);
                rs0 += f0.x + f0.y;
                rs1 += f1.x + f1.y;
            }
            {
                const int nt = 2 * kt + 1;
                __half2 e0 = h2exp(__floats2half2_rn(S[nt][0] - mn0, S[nt][1] - mn0));
                __half2 e1 = h2exp(__floats2half2_rn(S[nt][2] - mn1, S[nt][3] - mn1));
                aP[2] = *(uint32_t*)&e0;
                aP[3] = *(uint32_t*)&e1;
                float2 f0 = __half22float2(e0);
                float2 f1 = __half22float2(e1);
                rs0 += f0.x + f0.y;
                rs1 += f1.x + f1.y;
            }
#pragma unroll
            for (int np = 0; np < 4; np++) {
                uint32_t vB[4];
                ldsm4t(vB, vOff + sb + (kt * 16 + (lane & 15)) * 144 + np * 32 + (lane >> 4) * 16);
                mma_f16(O[np * 2],     aP, vB);
                mma_f16(O[np * 2 + 1], aP, vB + 2);
            }
        }
        rs0 += __shfl_xor_sync(0xffffffffu, rs0, 1);
        rs0 += __shfl_xor_sync(0xffffffffu, rs0, 2);
        rs1 += __shfl_xor_sync(0xffffffffu, rs1, 1);
        rs1 += __shfl_xor_sync(0xffffffffu, rs1, 2);
        l0 = l0 * sc0 + rs0;
        l1 = l1 * sc1 + rs1;

        __syncthreads();
        buf ^= 1;
    }

    // epilogue: normalize, write ctx as fp16 hi/lo
    const float il0 = 1.0f / l0, il1 = 1.0f / l1;
    const int row0 = q0 + warp * 16 + (lane >> 2);
    const size_t base0 = ((size_t)b * LL + row0) * CC + h * DD;
    const size_t base1 = base0 + (size_t)8 * CC;
#pragma unroll
    for (int nt = 0; nt < 8; nt++) {
        int col = nt * 8 + 2 * (lane & 3);
        {
            float o0 = O[nt][0] * il0, o1 = O[nt][1] * il0;
            __half h0 = __float2half_rn(o0), h1 = __float2half_rn(o1);
            __half2 hp; hp.x = h0; hp.y = h1;
            __half2 lp;
            lp.x = __float2half_rn(o0 - __half2float(h0));
            lp.y = __float2half_rn(o1 - __half2float(h1));
            *(__half2*)&g_ctxhi[base0 + col] = hp;
            *(__half2*)&g_ctxlo[base0 + col] = lp;
        }
        {
            float o0 = O[nt][2] * il1, o1 = O[nt][3] * il1;
            __half h0 = __float2half_rn(o0), h1 = __float2half_rn(o1);
            __half2 hp; hp.x = h0; hp.y = h1;
            __half2 lp;
            lp.x = __float2half_rn(o0 - __half2float(h0));
            lp.y = __float2half_rn(o1 - __half2float(h1));
            *(__half2*)&g_ctxhi[base1 + col] = hp;
            *(__half2*)&g_ctxlo[base1 + col] = lp;
        }
    }
}

// ---------------- launch -----------------------------------------------------
extern "C" void kernel_launch(void* const* d_in, const int* in_sizes, int n_in,
                              void* d_out, int out_size)
{
    const float* q  = (const float*)d_in[0];
    const void*  mk = d_in[1];
    const float* Wq = (const float*)d_in[2];
    const float* Wk = (const float*)d_in[3];
    const float* Wv = (const float*)d_in[4];
    const float* Wo = (const float*)d_in[5];
    const float* bo = (const float*)d_in[6];
    float* out = (float*)d_out;

    __half *xhi, *xlo, *w16, *chi, *clo;
    cudaGetSymbolAddress((void**)&xhi, g_xhi);
    cudaGetSymbolAddress((void**)&xlo, g_xlo);
    cudaGetSymbolAddress((void**)&w16, g_w16);
    cudaGetSymbolAddress((void**)&chi, g_ctxhi);
    cudaGetSymbolAddress((void**)&clo, g_ctxlo);

    cudaFuncSetAttribute(flash_kernel, cudaFuncAttributeMaxDynamicSharedMemorySize, FL_SMEM);
    cudaFuncSetAttribute(gemm_mma_kernel, cudaFuncAttributeMaxDynamicSharedMemorySize, GM_SMEM);

    prep_kernel<<<8464, 256>>>(q, mk, Wq, Wk, Wv, Wo);

    gemm_mma_kernel<<<dim3(CC/128, ML/128, 3), 256, GM_SMEM>>>(
        xhi, xlo, w16, nullptr, nullptr, 0);

    rope_apply_kernel<<<(BB*HH*LL*16 + 255) / 256, 256>>>();

    flash_kernel<<<dim3(LL/64, BB*HH), 128, FL_SMEM>>>();

    gemm_mma_kernel<<<dim3(CC/128, ML/128, 1), 256, GM_SMEM>>>(
        chi, clo, w16 + 3*(size_t)CC*CC, bo, out, 1);
}